// round 5
// baseline (speedup 1.0000x reference)
#include <cuda_runtime.h>
#include <cuda_fp16.h>
#include <math.h>
#include <stdint.h>

// ---------------- problem constants ----------------
#define B_SZ    512
#define LEAVES  256
#define HIDDEN  300
#define VOCAB   50000
#define P       320                  // padded feature pitch (fp16 elements)
#define EPITCH  304                  // embedding fp16 pitch (608B, 16B-aligned)
#define M0      (B_SZ * 2 * LEAVES)  // 262144 leaf rows
#define KP_LEAF 320
#define KP_H    640

// ---------------- GEMM tiling ----------------
#define BM     128
#define BK     16        // K per chunk (fp16) -> one m16n8k16 step
#define NSTAGE 4
#define APITCH 12        // u32 per row in smem (8 used + 4 pad) = 48B row stride
#define ATILE_U32 (BM * APITCH)      // 1536 u32 = 6144 B
#define BTILE_U32 (P * APITCH)       // 3840 u32 = 15360 B
#define STAGE_A_B (ATILE_U32 * 4)
#define STAGE_B_B (BTILE_U32 * 4)
#define OFF_B_BASE (NSTAGE * STAGE_A_B)
#define SMEM_TOT (NSTAGE * (STAGE_A_B + STAGE_B_B))   // 86016 B

// ---------------- device scratch ----------------
__device__ __align__(16) __half g_bufA[(size_t)M0 * P];
__device__ __align__(16) __half g_bufB[(size_t)(M0 / 2) * P];
__device__ __align__(16) __half g_embH[(size_t)VOCAB * EPITCH];
__device__ __align__(16) uint32_t g_BleafP[(KP_LEAF / BK) * BTILE_U32];  // 20 chunks
__device__ __align__(16) uint32_t g_BhP[(KP_H / BK) * BTILE_U32];        // 40 chunks
__device__ __align__(16) float g_bias[P];

// ---------------- PTX helpers ----------------
__device__ __forceinline__ uint32_t s2u(const void* p) {
    uint32_t a;
    asm("{.reg .u64 t; cvta.to.shared.u64 t, %1; cvt.u32.u64 %0, t;}" : "=r"(a) : "l"(p));
    return a;
}
__device__ __forceinline__ void cpa16(uint32_t dst, const void* src, int srcBytes) {
    asm volatile("cp.async.cg.shared.global [%0], [%1], 16, %2;\n"
                 :: "r"(dst), "l"(src), "r"(srcBytes));
}
__device__ __forceinline__ void cpa_commit() { asm volatile("cp.async.commit_group;\n"); }
template <int N> __device__ __forceinline__ void cpa_wait() {
    asm volatile("cp.async.wait_group %0;\n" :: "n"(N));
}
__device__ __forceinline__ void ldsm4(uint32_t* r, uint32_t addr) {
    asm volatile("ldmatrix.sync.aligned.m8n8.x4.shared.b16 {%0,%1,%2,%3}, [%4];"
                 : "=r"(r[0]), "=r"(r[1]), "=r"(r[2]), "=r"(r[3]) : "r"(addr));
}
__device__ __forceinline__ void mma_f16(float* d, const uint32_t* a, uint32_t b0, uint32_t b1) {
    asm volatile(
        "mma.sync.aligned.m16n8k16.row.col.f32.f16.f16.f32 "
        "{%0,%1,%2,%3}, {%4,%5,%6,%7}, {%8,%9}, {%0,%1,%2,%3};"
        : "+f"(d[0]), "+f"(d[1]), "+f"(d[2]), "+f"(d[3])
        : "r"(a[0]), "r"(a[1]), "r"(a[2]), "r"(a[3]), "r"(b0), "r"(b1));
}

// ---------------- prep kernels ----------------
__global__ void prep_embH(const float* __restrict__ e, __half* __restrict__ o, int n) {
    int i = blockIdx.x * blockDim.x + threadIdx.x;
    if (i >= n) return;
    int row = i / EPITCH, col = i % EPITCH;
    o[i] = __float2half_rn(col < HIDDEN ? e[row * HIDDEN + col] : 0.f);
}

#define TL_LEAF ((KP_LEAF / BK) * BTILE_U32)   // 76800
#define TL_TREE ((KP_H / BK) * BTILE_U32)      // 153600
// one kernel packs leaf B, tree B, and bias
__global__ void prep_weights(const float* __restrict__ Wl, const float* __restrict__ Wh,
                             const float* __restrict__ bh) {
    int e = blockIdx.x * blockDim.x + threadIdx.x;
    if (e < TL_LEAF) {
        int kt = e / BTILE_U32, rme = e % BTILE_U32;
        int n = rme / APITCH, k2 = rme % APITCH;
        float v0 = 0.f, v1 = 0.f;
        if (k2 < 8) {
            int k = kt * BK + 2 * k2;
            if (n < HIDDEN && k < HIDDEN)     v0 = Wl[n * HIDDEN + k];
            if (n < HIDDEN && k + 1 < HIDDEN) v1 = Wl[n * HIDDEN + k + 1];
        }
        __half2 h = __floats2half2_rn(v0, v1);
        g_BleafP[e] = *reinterpret_cast<uint32_t*>(&h);
        return;
    }
    e -= TL_LEAF;
    if (e < TL_TREE) {
        int kt = e / BTILE_U32, rme = e % BTILE_U32;
        int n = rme / APITCH, k2 = rme % APITCH;
        float v0 = 0.f, v1 = 0.f;
        if (k2 < 8) {
            int kg = kt * BK + 2 * k2;
            int half = (kg >= P) ? 1 : 0;
            int kk = kg - half * P;
            if (n < HIDDEN && kk < HIDDEN)     v0 = Wh[n * (2 * HIDDEN) + half * HIDDEN + kk];
            if (n < HIDDEN && kk + 1 < HIDDEN) v1 = Wh[n * (2 * HIDDEN) + half * HIDDEN + kk + 1];
        }
        __half2 h = __floats2half2_rn(v0, v1);
        g_BhP[e] = *reinterpret_cast<uint32_t*>(&h);
        return;
    }
    e -= TL_TREE;
    if (e < P) g_bias[e] = (e < HIDDEN) ? bh[e] : 0.f;
}

// ---------------- fp16 mma.sync GEMM ----------------
// C[M, 320](fp16) = A[M, Kp](fp16) @ Bpacked + bias.
// grid.x = M/128, 256 threads; warp grid 2(M) x 4(N), warp tile 64 x 80.
template <bool GATHER, bool BIAS>
__global__ __launch_bounds__(256)
void gemm_f16(const __half* __restrict__ A, const int* __restrict__ ids,
              const uint32_t* __restrict__ Bp, const float* __restrict__ bias,
              __half* __restrict__ C, int Kp) {
    extern __shared__ uint32_t smem[];
    const uint32_t sb = s2u(smem);
    const int t = threadIdx.x;
    const int wid = t >> 5, lane = t & 31;
    const int m0 = blockIdx.x * BM;
    const int KT = Kp / BK;

    // A loader: thread t handles row lm = t>>1, granule g = t&1 (8 halves each)
    const int lm = t >> 1, lg = t & 1;
    const __half* arow;
    if (GATHER) arow = A + (size_t)ids[m0 + lm] * EPITCH;
    else        arow = A + (size_t)(m0 + lm) * Kp;

    auto loadA = [&](int s, int kt) {
        int kstart = kt * BK + lg * 8;
        uint32_t dst = sb + s * STAGE_A_B + lm * 48 + lg * 16;
        int sz = 16;
        if (GATHER) sz = (kstart + 8 <= EPITCH) ? 16 : 0;
        cpa16(dst, arow + kstart, sz);
    };
    auto loadB = [&](int s, int kt) {
        const uint32_t* src = Bp + (size_t)kt * BTILE_U32;
        uint32_t dst = sb + OFF_B_BASE + s * STAGE_B_B;
#pragma unroll
        for (int i = 0; i < 4; i++) {
            int idx = t + i * 256;
            if (idx < BTILE_U32 / 4) cpa16(dst + idx * 16, src + idx * 4, 16);
        }
    };

    // warp coords
    const int wm  = wid >> 2;   // 0..1  (M)
    const int wnq = wid & 3;    // 0..3  (N)
    const int l = lane;
    // ldmatrix lane offsets (byte): A rows stride 48
    const uint32_t laneoffA = (uint32_t)(((l & 7) + ((l >> 3) & 1) * 8) * 48 + ((l >> 4) & 1) * 16);
    const uint32_t laneoffB = (uint32_t)(((l & 7) + ((l >> 4) & 1) * 8) * 48 + ((l >> 3) & 1) * 16);

    float acc[4][10][4];
#pragma unroll
    for (int mt = 0; mt < 4; mt++)
#pragma unroll
        for (int nt = 0; nt < 10; nt++)
#pragma unroll
            for (int q = 0; q < 4; q++) acc[mt][nt][q] = 0.f;

    // prologue: fill 3 stages
    loadA(0, 0); loadB(0, 0); cpa_commit();
    loadA(1, 1); loadB(1, 1); cpa_commit();
    loadA(2, 2); loadB(2, 2); cpa_commit();

    for (int kt = 0; kt < KT; kt++) {
        const int s = kt & 3;
        if (kt + 3 < KT) { loadA((kt + 3) & 3, kt + 3); loadB((kt + 3) & 3, kt + 3); }
        cpa_commit();
        cpa_wait<3>();
        __syncthreads();

        const uint32_t sA = sb + s * STAGE_A_B + (uint32_t)(wm * 64 * 48);
        const uint32_t sB = sb + OFF_B_BASE + s * STAGE_B_B + (uint32_t)(wnq * 80 * 48);

        uint32_t a[4][4];
#pragma unroll
        for (int mt = 0; mt < 4; mt++) ldsm4(a[mt], sA + mt * 768 + laneoffA);

#pragma unroll
        for (int p = 0; p < 5; p++) {
            uint32_t b[4];
            ldsm4(b, sB + p * 768 + laneoffB);
#pragma unroll
            for (int mt = 0; mt < 4; mt++) {
                mma_f16(acc[mt][2 * p],     a[mt], b[0], b[1]);
                mma_f16(acc[mt][2 * p + 1], a[mt], b[2], b[3]);
            }
        }
        __syncthreads();
    }

    // epilogue: bias + fp16 round + half2 stores
    const int r = lane >> 2, c = lane & 3;
#pragma unroll
    for (int mt = 0; mt < 4; mt++) {
        int row = m0 + wm * 64 + mt * 16 + r;
#pragma unroll
        for (int nt = 0; nt < 10; nt++) {
            int col = wnq * 80 + nt * 8 + 2 * c;
            float v0 = acc[mt][nt][0], v1 = acc[mt][nt][1];
            float v2 = acc[mt][nt][2], v3 = acc[mt][nt][3];
            if (BIAS) {
                float b0 = __ldg(bias + col), b1 = __ldg(bias + col + 1);
                v0 += b0; v1 += b1; v2 += b0; v3 += b1;
            }
            __half2 h0 = __floats2half2_rn(v0, v1);
            __half2 h1 = __floats2half2_rn(v2, v3);
            *reinterpret_cast<__half2*>(&C[(size_t)row * P + col])       = h0;
            *reinterpret_cast<__half2*>(&C[(size_t)(row + 8) * P + col]) = h1;
        }
    }
}

// ---------------- classifier ----------------
__global__ void classifier_kernel(const __half* __restrict__ roots,
                                  const float* __restrict__ Wc,
                                  const float* __restrict__ bc,
                                  float* __restrict__ out) {
    const int b = blockIdx.x;
    const __half* base = roots + (size_t)(2 * b) * P;
    float p0 = 0.f, p1 = 0.f, p2 = 0.f;
    for (int j = threadIdx.x; j < 2 * HIDDEN; j += blockDim.x) {
        int off = (j < HIDDEN) ? j : (j + (P - HIDDEN));
        float v = 1.f / (1.f + expf(-__half2float(base[off])));
        p0 += v * Wc[j];
        p1 += v * Wc[2 * HIDDEN + j];
        p2 += v * Wc[4 * HIDDEN + j];
    }
#pragma unroll
    for (int o = 16; o; o >>= 1) {
        p0 += __shfl_down_sync(0xffffffffu, p0, o);
        p1 += __shfl_down_sync(0xffffffffu, p1, o);
        p2 += __shfl_down_sync(0xffffffffu, p2, o);
    }
    __shared__ float red[3][4];
    int warp = threadIdx.x >> 5, lane = threadIdx.x & 31;
    if (lane == 0) { red[0][warp] = p0; red[1][warp] = p1; red[2][warp] = p2; }
    __syncthreads();
    if (threadIdx.x == 0) {
        float l0 = bc[0], l1 = bc[1], l2 = bc[2];
        int nw = blockDim.x >> 5;
        for (int w = 0; w < nw; w++) { l0 += red[0][w]; l1 += red[1][w]; l2 += red[2][w]; }
        float m = fmaxf(l0, fmaxf(l1, l2));
        float s = expf(l0 - m) + expf(l1 - m) + expf(l2 - m);
        float lse = m + logf(s);
        out[b * 3 + 0] = l0 - lse;
        out[b * 3 + 1] = l1 - lse;
        out[b * 3 + 2] = l2 - lse;
    }
}

// ---------------- kernel_launch ----------------
// inputs: 0 word_ids(int32) 1 embedding 2 W_leaf 3 W_h 4 b_h 5 W_cls 6 b_cls
extern "C" void kernel_launch(void* const* d_in, const int* in_sizes, int n_in,
                              void* d_out, int out_size) {
    const int*   word_ids  = (const int*)d_in[0];
    const float* embedding = (const float*)d_in[1];
    const float* W_leaf    = (const float*)d_in[2];
    const float* W_h       = (const float*)d_in[3];
    const float* b_h       = (const float*)d_in[4];
    const float* W_cls     = (const float*)d_in[5];
    const float* b_cls     = (const float*)d_in[6];
    float* out = (float*)d_out;

    __half *bufA, *bufB, *embH;
    uint32_t *bleaf, *bh;
    float *bias;
    cudaGetSymbolAddress((void**)&bufA, g_bufA);
    cudaGetSymbolAddress((void**)&bufB, g_bufB);
    cudaGetSymbolAddress((void**)&embH, g_embH);
    cudaGetSymbolAddress((void**)&bleaf, g_BleafP);
    cudaGetSymbolAddress((void**)&bh, g_BhP);
    cudaGetSymbolAddress((void**)&bias, g_bias);

    static bool attr_done = false;
    if (!attr_done) {
        cudaFuncSetAttribute(gemm_f16<true, false>,
                             cudaFuncAttributeMaxDynamicSharedMemorySize, SMEM_TOT);
        cudaFuncSetAttribute(gemm_f16<false, true>,
                             cudaFuncAttributeMaxDynamicSharedMemorySize, SMEM_TOT);
        attr_done = true;
    }

    {
        int n = VOCAB * EPITCH;
        prep_embH<<<(n + 255) / 256, 256>>>(embedding, embH, n);
        int tw = TL_LEAF + TL_TREE + P;
        prep_weights<<<(tw + 255) / 256, 256>>>(W_leaf, W_h, b_h);
    }

    // leaf: H0[262144, 320] = fp16(emb[ids]) @ Bleaf
    gemm_f16<true, false><<<M0 / BM, 256, SMEM_TOT>>>(embH, word_ids, bleaf, nullptr, bufA, KP_LEAF);

    // tree levels: view [2M, 320] as [M, 640]
    __half* cur = bufA;
    int M = M0;
    for (int l = 0; l < 8; l++) {
        M >>= 1;
        __half* nxt = (cur == bufA) ? bufB : bufA;
        gemm_f16<false, true><<<M / BM, 256, SMEM_TOT>>>(cur, nullptr, bh, bias, nxt, KP_H);
        cur = nxt;
    }

    classifier_kernel<<<B_SZ, 128>>>(cur, W_cls, b_cls, out);
    (void)in_sizes; (void)n_in; (void)out_size;
}

// round 6
// speedup vs baseline: 1.1596x; 1.1596x over previous
#include <cuda_runtime.h>
#include <cuda_fp16.h>
#include <math.h>
#include <stdint.h>

// ---------------- problem constants ----------------
#define B_SZ    512
#define LEAVES  256
#define HIDDEN  300
#define VOCAB   50000
#define P       320                  // padded feature pitch (fp16 elements)
#define EPITCH  304                  // embedding fp16 pitch (608B, 16B-aligned)
#define M0      (B_SZ * 2 * LEAVES)  // 262144 leaf rows
#define KP_LEAF 304                  // 19 chunks (trailing zeros trimmed)
#define KP_H    640

// ---------------- GEMM tiling ----------------
#define BM     64
#define BN     160       // per-CTA N (2 CTAs cover 320)
#define BK     16        // K per chunk -> one m16n8k16 step
#define NSTAGE 4
#define APITCH 12        // u32 per row (8 used + 4 pad) = 48B stride
#define ATILE_U32 (BM * APITCH)          // 768 u32 = 3072 B
#define BTILE_CTA_U32 (BN * APITCH)      // 1920 u32 = 7680 B
#define BTILE_FULL_U32 (P * APITCH)      // 3840 u32 (global packed image, full 320)
#define STAGE_A_B (ATILE_U32 * 4)
#define STAGE_B_B (BTILE_CTA_U32 * 4)
#define OFF_B_BASE (NSTAGE * STAGE_A_B)
#define SMEM_TOT (NSTAGE * (STAGE_A_B + STAGE_B_B))   // 43008 B

// ---------------- device scratch ----------------
__device__ __align__(16) __half g_bufA[(size_t)M0 * P];
__device__ __align__(16) __half g_bufB[(size_t)(M0 / 2) * P];
__device__ __align__(16) __half g_embH[(size_t)VOCAB * EPITCH];
__device__ __align__(16) uint32_t g_BleafP[(KP_LEAF / BK) * BTILE_FULL_U32];  // 19 chunks
__device__ __align__(16) uint32_t g_BhP[(KP_H / BK) * BTILE_FULL_U32];        // 40 chunks
__device__ __align__(16) float g_bias[P];

// ---------------- PTX helpers ----------------
__device__ __forceinline__ uint32_t s2u(const void* p) {
    uint32_t a;
    asm("{.reg .u64 t; cvta.to.shared.u64 t, %1; cvt.u32.u64 %0, t;}" : "=r"(a) : "l"(p));
    return a;
}
__device__ __forceinline__ void cpa16(uint32_t dst, const void* src, int srcBytes) {
    asm volatile("cp.async.cg.shared.global [%0], [%1], 16, %2;\n"
                 :: "r"(dst), "l"(src), "r"(srcBytes));
}
__device__ __forceinline__ void cpa_commit() { asm volatile("cp.async.commit_group;\n"); }
template <int N> __device__ __forceinline__ void cpa_wait() {
    asm volatile("cp.async.wait_group %0;\n" :: "n"(N));
}
__device__ __forceinline__ void ldsm4(uint32_t* r, uint32_t addr) {
    asm volatile("ldmatrix.sync.aligned.m8n8.x4.shared.b16 {%0,%1,%2,%3}, [%4];"
                 : "=r"(r[0]), "=r"(r[1]), "=r"(r[2]), "=r"(r[3]) : "r"(addr));
}
__device__ __forceinline__ void mma_f16(float* d, const uint32_t* a, uint32_t b0, uint32_t b1) {
    asm volatile(
        "mma.sync.aligned.m16n8k16.row.col.f32.f16.f16.f32 "
        "{%0,%1,%2,%3}, {%4,%5,%6,%7}, {%8,%9}, {%0,%1,%2,%3};"
        : "+f"(d[0]), "+f"(d[1]), "+f"(d[2]), "+f"(d[3])
        : "r"(a[0]), "r"(a[1]), "r"(a[2]), "r"(a[3]), "r"(b0), "r"(b1));
}

// ---------------- prep kernels ----------------
__global__ void prep_embH(const float* __restrict__ e, __half* __restrict__ o, int n) {
    int i = blockIdx.x * blockDim.x + threadIdx.x;
    if (i >= n) return;
    int row = i / EPITCH, col = i % EPITCH;
    o[i] = __float2half_rn(col < HIDDEN ? e[row * HIDDEN + col] : 0.f);
}

#define TL_LEAF ((KP_LEAF / BK) * BTILE_FULL_U32)   // 72960
#define TL_TREE ((KP_H / BK) * BTILE_FULL_U32)      // 153600
__global__ void prep_weights(const float* __restrict__ Wl, const float* __restrict__ Wh,
                             const float* __restrict__ bh) {
    int e = blockIdx.x * blockDim.x + threadIdx.x;
    if (e < TL_LEAF) {
        int kt = e / BTILE_FULL_U32, rme = e % BTILE_FULL_U32;
        int n = rme / APITCH, k2 = rme % APITCH;
        float v0 = 0.f, v1 = 0.f;
        if (k2 < 8) {
            int k = kt * BK + 2 * k2;
            if (n < HIDDEN && k < HIDDEN)     v0 = Wl[n * HIDDEN + k];
            if (n < HIDDEN && k + 1 < HIDDEN) v1 = Wl[n * HIDDEN + k + 1];
        }
        __half2 h = __floats2half2_rn(v0, v1);
        g_BleafP[e] = *reinterpret_cast<uint32_t*>(&h);
        return;
    }
    e -= TL_LEAF;
    if (e < TL_TREE) {
        int kt = e / BTILE_FULL_U32, rme = e % BTILE_FULL_U32;
        int n = rme / APITCH, k2 = rme % APITCH;
        float v0 = 0.f, v1 = 0.f;
        if (k2 < 8) {
            int kg = kt * BK + 2 * k2;
            int half = (kg >= P) ? 1 : 0;
            int kk = kg - half * P;
            if (n < HIDDEN && kk < HIDDEN)     v0 = Wh[n * (2 * HIDDEN) + half * HIDDEN + kk];
            if (n < HIDDEN && kk + 1 < HIDDEN) v1 = Wh[n * (2 * HIDDEN) + half * HIDDEN + kk + 1];
        }
        __half2 h = __floats2half2_rn(v0, v1);
        g_BhP[e] = *reinterpret_cast<uint32_t*>(&h);
        return;
    }
    e -= TL_TREE;
    if (e < P) g_bias[e] = (e < HIDDEN) ? bh[e] : 0.f;
}

// ---------------- fp16 mma.sync GEMM ----------------
// C[M, 320](fp16) = A[M, Kp](fp16) @ Bpacked + bias.
// grid = (M/64, 2); 256 thr; warp grid 4(M) x 2(N); warp tile 16 x 80; 40 acc/thr.
template <bool GATHER, bool BIAS>
__global__ __launch_bounds__(256, 3)
void gemm_f16(const __half* __restrict__ A, const int* __restrict__ ids,
              const uint32_t* __restrict__ Bp, const float* __restrict__ bias,
              __half* __restrict__ C, int Kp) {
    extern __shared__ uint32_t smem[];
    const uint32_t sb = s2u(smem);
    const int t = threadIdx.x;
    const int wid = t >> 5, lane = t & 31;
    const int m0 = blockIdx.x * BM;
    const int nb = blockIdx.y * BN;      // CTA N base (0 or 160)
    const int KT = Kp / BK;

    // A loader: threads 0..127, row lm = t>>1, granule lg = t&1
    const int lm = t >> 1, lg = t & 1;
    const __half* arow;
    if (GATHER) arow = A + (size_t)ids[m0 + lm] * EPITCH;
    else        arow = A + (size_t)(m0 + lm) * Kp;

    auto loadA = [&](int s, int kt) {
        if (t < 128) {
            int kstart = kt * BK + lg * 8;
            uint32_t dst = sb + s * STAGE_A_B + lm * 48 + lg * 16;
            cpa16(dst, arow + kstart, 16);
        }
    };
    auto loadB = [&](int s, int kt) {
        const uint32_t* src = Bp + (size_t)kt * BTILE_FULL_U32 + (size_t)nb * APITCH;
        uint32_t dst = sb + OFF_B_BASE + s * STAGE_B_B;
#pragma unroll
        for (int i = 0; i < 2; i++) {
            int idx = t + i * 256;
            if (idx < BTILE_CTA_U32 / 4) cpa16(dst + idx * 16, src + idx * 4, 16);
        }
    };

    // warp coords: 4(M) x 2(N)
    const int wm = wid >> 1;   // 0..3
    const int wn = wid & 1;    // 0..1
    const int l = lane;
    const uint32_t laneoffA = (uint32_t)(((l & 7) + ((l >> 3) & 1) * 8) * 48 + ((l >> 4) & 1) * 16);
    const uint32_t laneoffB = (uint32_t)(((l & 7) + ((l >> 4) & 1) * 8) * 48 + ((l >> 3) & 1) * 16);

    float acc[10][4];
#pragma unroll
    for (int nt = 0; nt < 10; nt++)
#pragma unroll
        for (int q = 0; q < 4; q++) acc[nt][q] = 0.f;

    // prologue: fill 3 stages
    loadA(0, 0); loadB(0, 0); cpa_commit();
    loadA(1, 1); loadB(1, 1); cpa_commit();
    loadA(2, 2); loadB(2, 2); cpa_commit();

    for (int kt = 0; kt < KT; kt++) {
        const int s = kt & 3;
        cpa_wait<2>();          // chunk kt resident
        __syncthreads();        // all threads past prior reads; safe to refill stage (kt-1)&3

        if (kt + 3 < KT) { loadA((kt + 3) & 3, kt + 3); loadB((kt + 3) & 3, kt + 3); }
        cpa_commit();

        const uint32_t sA = sb + s * STAGE_A_B + (uint32_t)(wm * 16 * 48);
        const uint32_t sB = sb + OFF_B_BASE + s * STAGE_B_B + (uint32_t)(wn * 80 * 48);

        uint32_t a[4];
        ldsm4(a, sA + laneoffA);
#pragma unroll
        for (int p = 0; p < 5; p++) {
            uint32_t b[4];
            ldsm4(b, sB + p * 768 + laneoffB);
            mma_f16(acc[2 * p],     a, b[0], b[1]);
            mma_f16(acc[2 * p + 1], a, b[2], b[3]);
        }
    }

    // epilogue: bias + fp16 round + half2 stores
    const int r = lane >> 2, c = lane & 3;
    const int row = m0 + wm * 16 + r;
#pragma unroll
    for (int nt = 0; nt < 10; nt++) {
        int col = nb + wn * 80 + nt * 8 + 2 * c;
        float v0 = acc[nt][0], v1 = acc[nt][1];
        float v2 = acc[nt][2], v3 = acc[nt][3];
        if (BIAS) {
            float b0 = __ldg(bias + col), b1 = __ldg(bias + col + 1);
            v0 += b0; v1 += b1; v2 += b0; v3 += b1;
        }
        __half2 h0 = __floats2half2_rn(v0, v1);
        __half2 h1 = __floats2half2_rn(v2, v3);
        *reinterpret_cast<__half2*>(&C[(size_t)row * P + col])       = h0;
        *reinterpret_cast<__half2*>(&C[(size_t)(row + 8) * P + col]) = h1;
    }
}

// ---------------- classifier ----------------
__global__ void classifier_kernel(const __half* __restrict__ roots,
                                  const float* __restrict__ Wc,
                                  const float* __restrict__ bc,
                                  float* __restrict__ out) {
    const int b = blockIdx.x;
    const __half* base = roots + (size_t)(2 * b) * P;
    float p0 = 0.f, p1 = 0.f, p2 = 0.f;
    for (int j = threadIdx.x; j < 2 * HIDDEN; j += blockDim.x) {
        int off = (j < HIDDEN) ? j : (j + (P - HIDDEN));
        float v = 1.f / (1.f + expf(-__half2float(base[off])));
        p0 += v * Wc[j];
        p1 += v * Wc[2 * HIDDEN + j];
        p2 += v * Wc[4 * HIDDEN + j];
    }
#pragma unroll
    for (int o = 16; o; o >>= 1) {
        p0 += __shfl_down_sync(0xffffffffu, p0, o);
        p1 += __shfl_down_sync(0xffffffffu, p1, o);
        p2 += __shfl_down_sync(0xffffffffu, p2, o);
    }
    __shared__ float red[3][4];
    int warp = threadIdx.x >> 5, lane = threadIdx.x & 31;
    if (lane == 0) { red[0][warp] = p0; red[1][warp] = p1; red[2][warp] = p2; }
    __syncthreads();
    if (threadIdx.x == 0) {
        float l0 = bc[0], l1 = bc[1], l2 = bc[2];
        int nw = blockDim.x >> 5;
        for (int w = 0; w < nw; w++) { l0 += red[0][w]; l1 += red[1][w]; l2 += red[2][w]; }
        float m = fmaxf(l0, fmaxf(l1, l2));
        float s = expf(l0 - m) + expf(l1 - m) + expf(l2 - m);
        float lse = m + logf(s);
        out[b * 3 + 0] = l0 - lse;
        out[b * 3 + 1] = l1 - lse;
        out[b * 3 + 2] = l2 - lse;
    }
}

// ---------------- kernel_launch ----------------
// inputs: 0 word_ids(int32) 1 embedding 2 W_leaf 3 W_h 4 b_h 5 W_cls 6 b_cls
extern "C" void kernel_launch(void* const* d_in, const int* in_sizes, int n_in,
                              void* d_out, int out_size) {
    const int*   word_ids  = (const int*)d_in[0];
    const float* embedding = (const float*)d_in[1];
    const float* W_leaf    = (const float*)d_in[2];
    const float* W_h       = (const float*)d_in[3];
    const float* b_h       = (const float*)d_in[4];
    const float* W_cls     = (const float*)d_in[5];
    const float* b_cls     = (const float*)d_in[6];
    float* out = (float*)d_out;

    __half *bufA, *bufB, *embH;
    uint32_t *bleaf, *bh;
    float *bias;
    cudaGetSymbolAddress((void**)&bufA, g_bufA);
    cudaGetSymbolAddress((void**)&bufB, g_bufB);
    cudaGetSymbolAddress((void**)&embH, g_embH);
    cudaGetSymbolAddress((void**)&bleaf, g_BleafP);
    cudaGetSymbolAddress((void**)&bh, g_BhP);
    cudaGetSymbolAddress((void**)&bias, g_bias);

    static bool attr_done = false;
    if (!attr_done) {
        cudaFuncSetAttribute(gemm_f16<true, false>,
                             cudaFuncAttributeMaxDynamicSharedMemorySize, SMEM_TOT);
        cudaFuncSetAttribute(gemm_f16<false, true>,
                             cudaFuncAttributeMaxDynamicSharedMemorySize, SMEM_TOT);
        attr_done = true;
    }

    {
        int n = VOCAB * EPITCH;
        prep_embH<<<(n + 255) / 256, 256>>>(embedding, embH, n);
        int tw = TL_LEAF + TL_TREE + P;
        prep_weights<<<(tw + 255) / 256, 256>>>(W_leaf, W_h, b_h);
    }

    // leaf: H0[262144, 320] = fp16(emb[ids]) @ Bleaf  (K = 304)
    {
        dim3 grid(M0 / BM, 2);
        gemm_f16<true, false><<<grid, 256, SMEM_TOT>>>(embH, word_ids, bleaf, nullptr, bufA, KP_LEAF);
    }

    // tree levels: view [2M, 320] as [M, 640]
    __half* cur = bufA;
    int M = M0;
    for (int l = 0; l < 8; l++) {
        M >>= 1;
        __half* nxt = (cur == bufA) ? bufB : bufA;
        dim3 grid(M / BM, 2);
        gemm_f16<false, true><<<grid, 256, SMEM_TOT>>>(cur, nullptr, bh, bias, nxt, KP_H);
        cur = nxt;
    }

    classifier_kernel<<<B_SZ, 128>>>(cur, W_cls, b_cls, out);
    (void)in_sizes; (void)n_in; (void)out_size;
}

// round 7
// speedup vs baseline: 1.4116x; 1.2174x over previous
#include <cuda_runtime.h>
#include <cuda_fp16.h>
#include <math.h>
#include <stdint.h>

// ---------------- problem constants ----------------
#define B_SZ    512
#define LEAVES  256
#define HIDDEN  300
#define VOCAB   50000
#define P       320                  // padded feature pitch (fp16 elements)
#define EPITCH  304                  // embedding fp16 pitch (608B, 16B-aligned)
#define M0      (B_SZ * 2 * LEAVES)  // 262144 leaf rows
#define KP_LEAF 304                  // 19 chunks
#define KP_H    640                  // 40 chunks

// ---------------- GEMM tiling ----------------
#define BM     64
#define BN     160       // per-CTA N (2 CTAs cover 320)
#define BK     16
#define NSTAGE 4
#define APITCH 12        // u32 per row (8 used + 4 pad) = 48B stride
#define ATILE_U32 (BM * APITCH)          // 768 u32 = 3072 B
#define BTILE_CTA_U32 (BN * APITCH)      // 1920 u32 = 7680 B
#define BTILE_FULL_U32 (P * APITCH)      // 3840 u32
#define STAGE_A_B (ATILE_U32 * 4)
#define STAGE_B_B (BTILE_CTA_U32 * 4)
#define OFF_B_BASE (NSTAGE * STAGE_A_B)
#define SMEM_TOT (NSTAGE * (STAGE_A_B + STAGE_B_B))   // 43008 B

// ---------------- device scratch ----------------
__device__ __align__(16) __half g_bufA[(size_t)M0 * P];
__device__ __align__(16) __half g_bufB[(size_t)(M0 / 2) * P];
__device__ __align__(16) __half g_embH[(size_t)VOCAB * EPITCH];
__device__ __align__(16) uint32_t g_BleafP[(KP_LEAF / BK) * BTILE_FULL_U32];
__device__ __align__(16) uint32_t g_BhP[(KP_H / BK) * BTILE_FULL_U32];
__device__ __align__(16) float g_bias[P];

// ---------------- PTX helpers ----------------
__device__ __forceinline__ uint32_t s2u(const void* p) {
    uint32_t a;
    asm("{.reg .u64 t; cvta.to.shared.u64 t, %1; cvt.u32.u64 %0, t;}" : "=r"(a) : "l"(p));
    return a;
}
__device__ __forceinline__ void cpa16(uint32_t dst, const void* src) {
    asm volatile("cp.async.cg.shared.global [%0], [%1], 16;\n" :: "r"(dst), "l"(src));
}
__device__ __forceinline__ void cpa_commit() { asm volatile("cp.async.commit_group;\n"); }
template <int N> __device__ __forceinline__ void cpa_wait() {
    asm volatile("cp.async.wait_group %0;\n" :: "n"(N));
}
__device__ __forceinline__ void ldsm4(uint32_t* r, uint32_t addr) {
    asm volatile("ldmatrix.sync.aligned.m8n8.x4.shared.b16 {%0,%1,%2,%3}, [%4];"
                 : "=r"(r[0]), "=r"(r[1]), "=r"(r[2]), "=r"(r[3]) : "r"(addr));
}
__device__ __forceinline__ void ldsm2(uint32_t* r, uint32_t addr) {
    asm volatile("ldmatrix.sync.aligned.m8n8.x2.shared.b16 {%0,%1}, [%2];"
                 : "=r"(r[0]), "=r"(r[1]) : "r"(addr));
}
__device__ __forceinline__ void mma_f16(float* d, const uint32_t* a, uint32_t b0, uint32_t b1) {
    asm volatile(
        "mma.sync.aligned.m16n8k16.row.col.f32.f16.f16.f32 "
        "{%0,%1,%2,%3}, {%4,%5,%6,%7}, {%8,%9}, {%0,%1,%2,%3};"
        : "+f"(d[0]), "+f"(d[1]), "+f"(d[2]), "+f"(d[3])
        : "r"(a[0]), "r"(a[1]), "r"(a[2]), "r"(a[3]), "r"(b0), "r"(b1));
}

// ---------------- prep kernels ----------------
__global__ void prep_embH(const float* __restrict__ e, __half* __restrict__ o, int n) {
    int i = blockIdx.x * blockDim.x + threadIdx.x;
    if (i >= n) return;
    int row = i / EPITCH, col = i % EPITCH;
    o[i] = __float2half_rn(col < HIDDEN ? e[row * HIDDEN + col] : 0.f);
}

#define TL_LEAF ((KP_LEAF / BK) * BTILE_FULL_U32)
#define TL_TREE ((KP_H / BK) * BTILE_FULL_U32)
__global__ void prep_weights(const float* __restrict__ Wl, const float* __restrict__ Wh,
                             const float* __restrict__ bh) {
    int e = blockIdx.x * blockDim.x + threadIdx.x;
    if (e < TL_LEAF) {
        int kt = e / BTILE_FULL_U32, rme = e % BTILE_FULL_U32;
        int n = rme / APITCH, k2 = rme % APITCH;
        float v0 = 0.f, v1 = 0.f;
        if (k2 < 8) {
            int k = kt * BK + 2 * k2;
            if (n < HIDDEN && k < HIDDEN)     v0 = Wl[n * HIDDEN + k];
            if (n < HIDDEN && k + 1 < HIDDEN) v1 = Wl[n * HIDDEN + k + 1];
        }
        __half2 h = __floats2half2_rn(v0, v1);
        g_BleafP[e] = *reinterpret_cast<uint32_t*>(&h);
        return;
    }
    e -= TL_LEAF;
    if (e < TL_TREE) {
        int kt = e / BTILE_FULL_U32, rme = e % BTILE_FULL_U32;
        int n = rme / APITCH, k2 = rme % APITCH;
        float v0 = 0.f, v1 = 0.f;
        if (k2 < 8) {
            int kg = kt * BK + 2 * k2;
            int half = (kg >= P) ? 1 : 0;
            int kk = kg - half * P;
            if (n < HIDDEN && kk < HIDDEN)     v0 = Wh[n * (2 * HIDDEN) + half * HIDDEN + kk];
            if (n < HIDDEN && kk + 1 < HIDDEN) v1 = Wh[n * (2 * HIDDEN) + half * HIDDEN + kk + 1];
        }
        __half2 h = __floats2half2_rn(v0, v1);
        g_BhP[e] = *reinterpret_cast<uint32_t*>(&h);
        return;
    }
    e -= TL_TREE;
    if (e < P) g_bias[e] = (e < HIDDEN) ? bh[e] : 0.f;
}

// ---------------- fp16 mma.sync GEMM ----------------
// C[M, 320](fp16) = A[M, Kp](fp16) @ Bpacked + bias.
// grid = (M/64, 2); 128 thr (4 warps); warp grid 1(M) x 4(N); warp tile 64 x 40.
// LDSM/chunk = 4(A x4) + 2(B x4) + 1(B x2) per warp; B loaded once across CTA.
template <bool GATHER, bool BIAS>
__global__ __launch_bounds__(128, 4)
void gemm_f16(const __half* __restrict__ A, const int* __restrict__ ids,
              const uint32_t* __restrict__ Bp, const float* __restrict__ bias,
              __half* __restrict__ C, int Kp) {
    extern __shared__ uint32_t smem[];
    const uint32_t sb = s2u(smem);
    const int t = threadIdx.x;
    const int wid = t >> 5, lane = t & 31;
    const int m0 = blockIdx.x * BM;
    const int nb = blockIdx.y * BN;
    const int KT = Kp / BK;

    // A loader: 128 threads, row lm = t>>1, granule lg = t&1 (16B each) = 3072B
    const int lm = t >> 1, lg = t & 1;
    const __half* arow;
    if (GATHER) arow = A + (size_t)ids[m0 + lm] * EPITCH;
    else        arow = A + (size_t)(m0 + lm) * Kp;

    auto loadA = [&](int s, int kt) {
        int kstart = kt * BK + lg * 8;
        uint32_t dst = sb + s * STAGE_A_B + lm * 48 + lg * 16;
        cpa16(dst, arow + kstart);
    };
    auto loadB = [&](int s, int kt) {
        const uint32_t* src = Bp + (size_t)kt * BTILE_FULL_U32 + (size_t)nb * APITCH;
        uint32_t dst = sb + OFF_B_BASE + s * STAGE_B_B;
#pragma unroll
        for (int i = 0; i < 4; i++) {
            int idx = t + i * 128;
            if (idx < BTILE_CTA_U32 / 4) cpa16(dst + idx * 16, src + idx * 4);
        }
    };

    const int l = lane;
    const uint32_t laneoffA = (uint32_t)(((l & 7) + ((l >> 3) & 1) * 8) * 48 + ((l >> 4) & 1) * 16);
    const uint32_t laneoffB = (uint32_t)(((l & 7) + ((l >> 4) & 1) * 8) * 48 + ((l >> 3) & 1) * 16);
    const uint32_t laneoffB2 = (uint32_t)((l & 7) * 48 + (((l >> 3) & 1) * 16));  // lanes 0-15 used

    float acc[4][5][4];
#pragma unroll
    for (int mt = 0; mt < 4; mt++)
#pragma unroll
        for (int nt = 0; nt < 5; nt++)
#pragma unroll
            for (int q = 0; q < 4; q++) acc[mt][nt][q] = 0.f;

    // prologue
    loadA(0, 0); loadB(0, 0); cpa_commit();
    loadA(1, 1); loadB(1, 1); cpa_commit();
    loadA(2, 2); loadB(2, 2); cpa_commit();

    for (int kt = 0; kt < KT; kt++) {
        const int s = kt & 3;
        cpa_wait<2>();
        __syncthreads();

        if (kt + 3 < KT) { loadA((kt + 3) & 3, kt + 3); loadB((kt + 3) & 3, kt + 3); }
        cpa_commit();

        const uint32_t sA = sb + s * STAGE_A_B;
        const uint32_t sB = sb + OFF_B_BASE + s * STAGE_B_B + (uint32_t)(wid * 40 * 48);

        uint32_t a[4][4];
#pragma unroll
        for (int mt = 0; mt < 4; mt++) ldsm4(a[mt], sA + mt * 768 + laneoffA);

        // B cols 0..31 via two x4, cols 32..39 via x2
#pragma unroll
        for (int p = 0; p < 2; p++) {
            uint32_t b[4];
            ldsm4(b, sB + p * 768 + laneoffB);
#pragma unroll
            for (int mt = 0; mt < 4; mt++) {
                mma_f16(acc[mt][2 * p],     a[mt], b[0], b[1]);
                mma_f16(acc[mt][2 * p + 1], a[mt], b[2], b[3]);
            }
        }
        {
            uint32_t b[2];
            ldsm2(b, sB + 2 * 768 + laneoffB2);
#pragma unroll
            for (int mt = 0; mt < 4; mt++) mma_f16(acc[mt][4], a[mt], b[0], b[1]);
        }
    }

    // epilogue
    const int r = lane >> 2, c = lane & 3;
#pragma unroll
    for (int mt = 0; mt < 4; mt++) {
        int row = m0 + mt * 16 + r;
#pragma unroll
        for (int nt = 0; nt < 5; nt++) {
            int col = nb + wid * 40 + nt * 8 + 2 * c;
            float v0 = acc[mt][nt][0], v1 = acc[mt][nt][1];
            float v2 = acc[mt][nt][2], v3 = acc[mt][nt][3];
            if (BIAS) {
                float b0 = __ldg(bias + col), b1 = __ldg(bias + col + 1);
                v0 += b0; v1 += b1; v2 += b0; v3 += b1;
            }
            __half2 h0 = __floats2half2_rn(v0, v1);
            __half2 h1 = __floats2half2_rn(v2, v3);
            *reinterpret_cast<__half2*>(&C[(size_t)row * P + col])       = h0;
            *reinterpret_cast<__half2*>(&C[(size_t)(row + 8) * P + col]) = h1;
        }
    }
}

// ---------------- classifier ----------------
__global__ void classifier_kernel(const __half* __restrict__ roots,
                                  const float* __restrict__ Wc,
                                  const float* __restrict__ bc,
                                  float* __restrict__ out) {
    const int b = blockIdx.x;
    const __half* base = roots + (size_t)(2 * b) * P;
    float p0 = 0.f, p1 = 0.f, p2 = 0.f;
    for (int j = threadIdx.x; j < 2 * HIDDEN; j += blockDim.x) {
        int off = (j < HIDDEN) ? j : (j + (P - HIDDEN));
        float v = 1.f / (1.f + expf(-__half2float(base[off])));
        p0 += v * Wc[j];
        p1 += v * Wc[2 * HIDDEN + j];
        p2 += v * Wc[4 * HIDDEN + j];
    }
#pragma unroll
    for (int o = 16; o; o >>= 1) {
        p0 += __shfl_down_sync(0xffffffffu, p0, o);
        p1 += __shfl_down_sync(0xffffffffu, p1, o);
        p2 += __shfl_down_sync(0xffffffffu, p2, o);
    }
    __shared__ float red[3][4];
    int warp = threadIdx.x >> 5, lane = threadIdx.x & 31;
    if (lane == 0) { red[0][warp] = p0; red[1][warp] = p1; red[2][warp] = p2; }
    __syncthreads();
    if (threadIdx.x == 0) {
        float l0 = bc[0], l1 = bc[1], l2 = bc[2];
        int nw = blockDim.x >> 5;
        for (int w = 0; w < nw; w++) { l0 += red[0][w]; l1 += red[1][w]; l2 += red[2][w]; }
        float m = fmaxf(l0, fmaxf(l1, l2));
        float s = expf(l0 - m) + expf(l1 - m) + expf(l2 - m);
        float lse = m + logf(s);
        out[b * 3 + 0] = l0 - lse;
        out[b * 3 + 1] = l1 - lse;
        out[b * 3 + 2] = l2 - lse;
    }
}

// ---------------- kernel_launch ----------------
extern "C" void kernel_launch(void* const* d_in, const int* in_sizes, int n_in,
                              void* d_out, int out_size) {
    const int*   word_ids  = (const int*)d_in[0];
    const float* embedding = (const float*)d_in[1];
    const float* W_leaf    = (const float*)d_in[2];
    const float* W_h       = (const float*)d_in[3];
    const float* b_h       = (const float*)d_in[4];
    const float* W_cls     = (const float*)d_in[5];
    const float* b_cls     = (const float*)d_in[6];
    float* out = (float*)d_out;

    __half *bufA, *bufB, *embH;
    uint32_t *bleaf, *bh;
    float *bias;
    cudaGetSymbolAddress((void**)&bufA, g_bufA);
    cudaGetSymbolAddress((void**)&bufB, g_bufB);
    cudaGetSymbolAddress((void**)&embH, g_embH);
    cudaGetSymbolAddress((void**)&bleaf, g_BleafP);
    cudaGetSymbolAddress((void**)&bh, g_BhP);
    cudaGetSymbolAddress((void**)&bias, g_bias);

    static bool attr_done = false;
    if (!attr_done) {
        cudaFuncSetAttribute(gemm_f16<true, false>,
                             cudaFuncAttributeMaxDynamicSharedMemorySize, SMEM_TOT);
        cudaFuncSetAttribute(gemm_f16<false, true>,
                             cudaFuncAttributeMaxDynamicSharedMemorySize, SMEM_TOT);
        attr_done = true;
    }

    {
        int n = VOCAB * EPITCH;
        prep_embH<<<(n + 255) / 256, 256>>>(embedding, embH, n);
        int tw = TL_LEAF + TL_TREE + P;
        prep_weights<<<(tw + 255) / 256, 256>>>(W_leaf, W_h, b_h);
    }

    // leaf: H0[262144, 320] = fp16(emb[ids]) @ Bleaf  (K = 304)
    {
        dim3 grid(M0 / BM, 2);
        gemm_f16<true, false><<<grid, 128, SMEM_TOT>>>(embH, word_ids, bleaf, nullptr, bufA, KP_LEAF);
    }

    // tree levels: view [2M, 320] as [M, 640]
    __half* cur = bufA;
    int M = M0;
    for (int l = 0; l < 8; l++) {
        M >>= 1;
        __half* nxt = (cur == bufA) ? bufB : bufA;
        dim3 grid(M / BM, 2);
        gemm_f16<false, true><<<grid, 128, SMEM_TOT>>>(cur, nullptr, bh, bias, nxt, KP_H);
        cur = nxt;
    }

    classifier_kernel<<<B_SZ, 128>>>(cur, W_cls, b_cls, out);
    (void)in_sizes; (void)n_in; (void)out_size;
}

// round 8
// speedup vs baseline: 1.5369x; 1.0887x over previous
#include <cuda_runtime.h>
#include <cuda_fp16.h>
#include <math.h>
#include <stdint.h>

// ---------------- problem constants ----------------
#define B_SZ    512
#define LEAVES  256
#define HIDDEN  300
#define VOCAB   50000
#define P       320                  // padded feature pitch (fp16 elements)
#define EPITCH  304                  // embedding fp16 pitch (608B, 16B-aligned)
#define M0      (B_SZ * 2 * LEAVES)  // 262144 leaf rows
#define KP_LEAF 304                  // 19 chunks
#define KP_H    640                  // 40 chunks

// ---------------- GEMM tiling ----------------
#define BM     64
#define BN     160       // per-CTA N (2 CTAs cover 320)
#define BK     16
#define NSTAGE 4
// compact layout: 32B row pitch (8 u32), XOR swizzle on 16B granule
#define ATILE_B   2048                   // 64 rows * 32B
#define BTILE_B   5120                   // 160 rows * 32B
#define CHUNK_U32 2560                   // full-320-row packed chunk (320*8 u32)
#define OFF_B_BASE (NSTAGE * ATILE_B)    // 8192
#define SMEM_TOT (NSTAGE * (ATILE_B + BTILE_B))   // 28672 B

// ---------------- device scratch ----------------
__device__ __align__(16) __half g_bufA[(size_t)M0 * P];
__device__ __align__(16) __half g_bufB[(size_t)(M0 / 2) * P];
__device__ __align__(16) __half g_embH[(size_t)VOCAB * EPITCH];
__device__ __align__(16) uint32_t g_BleafP[(KP_LEAF / BK) * CHUNK_U32];
__device__ __align__(16) uint32_t g_BhP[(KP_H / BK) * CHUNK_U32];
__device__ __align__(16) float g_bias[P];

// ---------------- PTX helpers ----------------
__device__ __forceinline__ uint32_t s2u(const void* p) {
    uint32_t a;
    asm("{.reg .u64 t; cvta.to.shared.u64 t, %1; cvt.u32.u64 %0, t;}" : "=r"(a) : "l"(p));
    return a;
}
__device__ __forceinline__ void cpa16(uint32_t dst, const void* src) {
    asm volatile("cp.async.cg.shared.global [%0], [%1], 16;\n" :: "r"(dst), "l"(src));
}
__device__ __forceinline__ void cpa_commit() { asm volatile("cp.async.commit_group;\n"); }
template <int N> __device__ __forceinline__ void cpa_wait() {
    asm volatile("cp.async.wait_group %0;\n" :: "n"(N));
}
__device__ __forceinline__ void ldsm4(uint32_t* r, uint32_t addr) {
    asm volatile("ldmatrix.sync.aligned.m8n8.x4.shared.b16 {%0,%1,%2,%3}, [%4];"
                 : "=r"(r[0]), "=r"(r[1]), "=r"(r[2]), "=r"(r[3]) : "r"(addr));
}
__device__ __forceinline__ void ldsm2(uint32_t* r, uint32_t addr) {
    asm volatile("ldmatrix.sync.aligned.m8n8.x2.shared.b16 {%0,%1}, [%2];"
                 : "=r"(r[0]), "=r"(r[1]) : "r"(addr));
}
__device__ __forceinline__ void mma_f16(float* d, const uint32_t* a, uint32_t b0, uint32_t b1) {
    asm volatile(
        "mma.sync.aligned.m16n8k16.row.col.f32.f16.f16.f32 "
        "{%0,%1,%2,%3}, {%4,%5,%6,%7}, {%8,%9}, {%0,%1,%2,%3};"
        : "+f"(d[0]), "+f"(d[1]), "+f"(d[2]), "+f"(d[3])
        : "r"(a[0]), "r"(a[1]), "r"(a[2]), "r"(a[3]), "r"(b0), "r"(b1));
}

// ---------------- prep kernels ----------------
__global__ void prep_embH(const float* __restrict__ e, __half* __restrict__ o, int n) {
    int i = blockIdx.x * blockDim.x + threadIdx.x;
    if (i >= n) return;
    int row = i / EPITCH, col = i % EPITCH;
    o[i] = __float2half_rn(col < HIDDEN ? e[row * HIDDEN + col] : 0.f);
}

// Packed B image per BK16 chunk: row n (8 u32 = 32B), 16B granule position
// gs holds logical granule g = gs ^ ((n>>2)&1); u32 w in granule -> k = 16*kt + g*8 + w*2
#define TL_LEAF ((KP_LEAF / BK) * CHUNK_U32)   // 48640
#define TL_TREE ((KP_H / BK) * CHUNK_U32)      // 102400
__global__ void prep_weights(const float* __restrict__ Wl, const float* __restrict__ Wh,
                             const float* __restrict__ bh) {
    int e = blockIdx.x * blockDim.x + threadIdx.x;
    if (e < TL_LEAF) {
        int kt = e / CHUNK_U32, rme = e % CHUNK_U32;
        int n = rme >> 3, q = rme & 7;
        int g = (q >> 2) ^ ((n >> 2) & 1);
        int k = kt * BK + g * 8 + (q & 3) * 2;
        float v0 = 0.f, v1 = 0.f;
        if (n < HIDDEN && k < HIDDEN)     v0 = Wl[n * HIDDEN + k];
        if (n < HIDDEN && k + 1 < HIDDEN) v1 = Wl[n * HIDDEN + k + 1];
        __half2 h = __floats2half2_rn(v0, v1);
        g_BleafP[e] = *reinterpret_cast<uint32_t*>(&h);
        return;
    }
    e -= TL_LEAF;
    if (e < TL_TREE) {
        int kt = e / CHUNK_U32, rme = e % CHUNK_U32;
        int n = rme >> 3, q = rme & 7;
        int g = (q >> 2) ^ ((n >> 2) & 1);
        int kg = kt * BK + g * 8 + (q & 3) * 2;
        int half = (kg >= P) ? 1 : 0;
        int kk = kg - half * P;
        float v0 = 0.f, v1 = 0.f;
        if (n < HIDDEN && kk < HIDDEN)     v0 = Wh[n * (2 * HIDDEN) + half * HIDDEN + kk];
        if (n < HIDDEN && kk + 1 < HIDDEN) v1 = Wh[n * (2 * HIDDEN) + half * HIDDEN + kk + 1];
        __half2 h = __floats2half2_rn(v0, v1);
        g_BhP[e] = *reinterpret_cast<uint32_t*>(&h);
        return;
    }
    e -= TL_TREE;
    if (e < P) g_bias[e] = (e < HIDDEN) ? bh[e] : 0.f;
}

// ---------------- fp16 mma.sync GEMM ----------------
// grid = (M/64, 2); 128 thr; warp grid 1(M) x 4(N); warp tile 64 x 40.
// Compact smem (32B pitch + XOR-granule swizzle): conflict-free LDSM, minimal fill.
template <bool GATHER, bool BIAS>
__global__ __launch_bounds__(128, 4)
void gemm_f16(const __half* __restrict__ A, const int* __restrict__ ids,
              const uint32_t* __restrict__ Bp, const float* __restrict__ bias,
              __half* __restrict__ C, int Kp) {
    extern __shared__ uint32_t smem[];
    const uint32_t sb = s2u(smem);
    const int t = threadIdx.x;
    const int wid = t >> 5, lane = t & 31;
    const int m0 = blockIdx.x * BM;
    const int nb = blockIdx.y * BN;
    const int KT = Kp / BK;

    // A loader: row lm = t>>1, granule lg = t&1 (16B), swizzled store
    const int lm = t >> 1, lg = t & 1;
    const __half* arow;
    if (GATHER) arow = A + (size_t)ids[m0 + lm] * EPITCH;
    else        arow = A + (size_t)(m0 + lm) * Kp;
    const uint32_t aDstOff = (uint32_t)(lm * 32 + ((lg ^ ((lm >> 2) & 1)) << 4));

    auto loadA = [&](int s, int kt) {
        cpa16(sb + s * ATILE_B + aDstOff, arow + kt * BK + lg * 8);
    };
    auto loadB = [&](int s, int kt) {
        const uint32_t* src = Bp + (size_t)kt * CHUNK_U32 + (size_t)nb * 8;
        uint32_t dst = sb + OFF_B_BASE + s * BTILE_B;
#pragma unroll
        for (int i = 0; i < 3; i++) {
            int idx = t + i * 128;
            if (idx < BTILE_B / 16) cpa16(dst + idx * 16, src + idx * 4);
        }
    };

    const int l = lane;
    {
    }
    const int rowA = (l & 7) + ((l >> 3) & 1) * 8;
    const uint32_t laneoffA = (uint32_t)(rowA * 32 + ((((l >> 4) & 1) ^ ((rowA >> 2) & 1)) << 4));
    const int rowB = (l & 7) + ((l >> 4) & 1) * 8;
    const uint32_t laneoffB = (uint32_t)(rowB * 32 + ((((l >> 3) & 1) ^ ((rowB >> 2) & 1)) << 4));
    const int rowB2 = l & 7;
    const uint32_t laneoffB2 = (uint32_t)(rowB2 * 32 + ((((l >> 3) & 1) ^ ((rowB2 >> 2) & 1)) << 4));

    float acc[4][5][4];
#pragma unroll
    for (int mt = 0; mt < 4; mt++)
#pragma unroll
        for (int nt = 0; nt < 5; nt++)
#pragma unroll
            for (int q = 0; q < 4; q++) acc[mt][nt][q] = 0.f;

    // prologue
    loadA(0, 0); loadB(0, 0); cpa_commit();
    loadA(1, 1); loadB(1, 1); cpa_commit();
    loadA(2, 2); loadB(2, 2); cpa_commit();

    for (int kt = 0; kt < KT; kt++) {
        const int s = kt & 3;
        cpa_wait<2>();
        __syncthreads();

        if (kt + 3 < KT) { loadA((kt + 3) & 3, kt + 3); loadB((kt + 3) & 3, kt + 3); }
        cpa_commit();

        const uint32_t sA = sb + s * ATILE_B;
        const uint32_t sB = sb + OFF_B_BASE + s * BTILE_B + (uint32_t)(wid * 40 * 32);

        uint32_t a[4][4];
#pragma unroll
        for (int mt = 0; mt < 4; mt++) ldsm4(a[mt], sA + mt * 512 + laneoffA);

#pragma unroll
        for (int p = 0; p < 2; p++) {
            uint32_t b[4];
            ldsm4(b, sB + p * 512 + laneoffB);
#pragma unroll
            for (int mt = 0; mt < 4; mt++) {
                mma_f16(acc[mt][2 * p],     a[mt], b[0], b[1]);
                mma_f16(acc[mt][2 * p + 1], a[mt], b[2], b[3]);
            }
        }
        {
            uint32_t b[2];
            ldsm2(b, sB + 1024 + laneoffB2);
#pragma unroll
            for (int mt = 0; mt < 4; mt++) mma_f16(acc[mt][4], a[mt], b[0], b[1]);
        }
    }

    // epilogue
    const int r = lane >> 2, c = lane & 3;
#pragma unroll
    for (int mt = 0; mt < 4; mt++) {
        int row = m0 + mt * 16 + r;
#pragma unroll
        for (int nt = 0; nt < 5; nt++) {
            int col = nb + wid * 40 + nt * 8 + 2 * c;
            float v0 = acc[mt][nt][0], v1 = acc[mt][nt][1];
            float v2 = acc[mt][nt][2], v3 = acc[mt][nt][3];
            if (BIAS) {
                float b0 = __ldg(bias + col), b1 = __ldg(bias + col + 1);
                v0 += b0; v1 += b1; v2 += b0; v3 += b1;
            }
            __half2 h0 = __floats2half2_rn(v0, v1);
            __half2 h1 = __floats2half2_rn(v2, v3);
            *reinterpret_cast<__half2*>(&C[(size_t)row * P + col])       = h0;
            *reinterpret_cast<__half2*>(&C[(size_t)(row + 8) * P + col]) = h1;
        }
    }
}

// ---------------- classifier ----------------
__global__ void classifier_kernel(const __half* __restrict__ roots,
                                  const float* __restrict__ Wc,
                                  const float* __restrict__ bc,
                                  float* __restrict__ out) {
    const int b = blockIdx.x;
    const __half* base = roots + (size_t)(2 * b) * P;
    float p0 = 0.f, p1 = 0.f, p2 = 0.f;
    for (int j = threadIdx.x; j < 2 * HIDDEN; j += blockDim.x) {
        int off = (j < HIDDEN) ? j : (j + (P - HIDDEN));
        float v = 1.f / (1.f + expf(-__half2float(base[off])));
        p0 += v * Wc[j];
        p1 += v * Wc[2 * HIDDEN + j];
        p2 += v * Wc[4 * HIDDEN + j];
    }
#pragma unroll
    for (int o = 16; o; o >>= 1) {
        p0 += __shfl_down_sync(0xffffffffu, p0, o);
        p1 += __shfl_down_sync(0xffffffffu, p1, o);
        p2 += __shfl_down_sync(0xffffffffu, p2, o);
    }
    __shared__ float red[3][4];
    int warp = threadIdx.x >> 5, lane = threadIdx.x & 31;
    if (lane == 0) { red[0][warp] = p0; red[1][warp] = p1; red[2][warp] = p2; }
    __syncthreads();
    if (threadIdx.x == 0) {
        float l0 = bc[0], l1 = bc[1], l2 = bc[2];
        int nw = blockDim.x >> 5;
        for (int w = 0; w < nw; w++) { l0 += red[0][w]; l1 += red[1][w]; l2 += red[2][w]; }
        float m = fmaxf(l0, fmaxf(l1, l2));
        float s = expf(l0 - m) + expf(l1 - m) + expf(l2 - m);
        float lse = m + logf(s);
        out[b * 3 + 0] = l0 - lse;
        out[b * 3 + 1] = l1 - lse;
        out[b * 3 + 2] = l2 - lse;
    }
}

// ---------------- kernel_launch ----------------
extern "C" void kernel_launch(void* const* d_in, const int* in_sizes, int n_in,
                              void* d_out, int out_size) {
    const int*   word_ids  = (const int*)d_in[0];
    const float* embedding = (const float*)d_in[1];
    const float* W_leaf    = (const float*)d_in[2];
    const float* W_h       = (const float*)d_in[3];
    const float* b_h       = (const float*)d_in[4];
    const float* W_cls     = (const float*)d_in[5];
    const float* b_cls     = (const float*)d_in[6];
    float* out = (float*)d_out;

    __half *bufA, *bufB, *embH;
    uint32_t *bleaf, *bh;
    float *bias;
    cudaGetSymbolAddress((void**)&bufA, g_bufA);
    cudaGetSymbolAddress((void**)&bufB, g_bufB);
    cudaGetSymbolAddress((void**)&embH, g_embH);
    cudaGetSymbolAddress((void**)&bleaf, g_BleafP);
    cudaGetSymbolAddress((void**)&bh, g_BhP);
    cudaGetSymbolAddress((void**)&bias, g_bias);

    {
        int n = VOCAB * EPITCH;
        prep_embH<<<(n + 255) / 256, 256>>>(embedding, embH, n);
        int tw = TL_LEAF + TL_TREE + P;
        prep_weights<<<(tw + 255) / 256, 256>>>(W_leaf, W_h, b_h);
    }

    // leaf: H0[262144, 320] = fp16(emb[ids]) @ Bleaf  (K = 304)
    {
        dim3 grid(M0 / BM, 2);
        gemm_f16<true, false><<<grid, 128, SMEM_TOT>>>(embH, word_ids, bleaf, nullptr, bufA, KP_LEAF);
    }

    // tree levels: view [2M, 320] as [M, 640]
    __half* cur = bufA;
    int M = M0;
    for (int l = 0; l < 8; l++) {
        M >>= 1;
        __half* nxt = (cur == bufA) ? bufB : bufA;
        dim3 grid(M / BM, 2);
        gemm_f16<false, true><<<grid, 128, SMEM_TOT>>>(cur, nullptr, bh, bias, nxt, KP_H);
        cur = nxt;
    }

    classifier_kernel<<<B_SZ, 128>>>(cur, W_cls, b_cls, out);
    (void)in_sizes; (void)n_in; (void)out_size;
}